// round 6
// baseline (speedup 1.0000x reference)
#include <cuda_runtime.h>
#include <cstdint>

// Elementwise ReLU, HBM-bound streaming kernel.
// 2^27 fp32 = 1 GiB traffic (512 MiB R + 512 MiB W).
// Evidence so far: R1 (unroll4, default ops, occ8): kernel 165.3us, DRAM 78.4%.
//                  R3 (unroll8, .cs both, occ5):    kernel 166.7us, DRAM 77.6%.
// -> occupancy and L2 allocation policy are both non-factors; we sit at the
//    mixed R/W HBM ceiling (~6.2 TB/s). This round isolates ONE remaining
//    knob: evict-first on STORES only (prompt dirty-sector drain), on top of
//    the best-measured R1 operating point (unroll 4, 32 regs, occ 8).

__global__ __launch_bounds__(256, 8) void relu_f4_kernel(
    const float4* __restrict__ in, float4* __restrict__ out, int n4)
{
    const int idx = blockIdx.x * blockDim.x + threadIdx.x;
    const int stride = gridDim.x * blockDim.x;
    const int stride4 = stride * 4;

    int i = idx;
    #pragma unroll 1
    for (; i + 3 * stride < n4; i += stride4) {
        float4 a = __ldg(&in[i]);
        float4 b = __ldg(&in[i + stride]);
        float4 c = __ldg(&in[i + 2 * stride]);
        float4 d = __ldg(&in[i + 3 * stride]);
        a.x = fmaxf(a.x, 0.f); a.y = fmaxf(a.y, 0.f); a.z = fmaxf(a.z, 0.f); a.w = fmaxf(a.w, 0.f);
        b.x = fmaxf(b.x, 0.f); b.y = fmaxf(b.y, 0.f); b.z = fmaxf(b.z, 0.f); b.w = fmaxf(b.w, 0.f);
        c.x = fmaxf(c.x, 0.f); c.y = fmaxf(c.y, 0.f); c.z = fmaxf(c.z, 0.f); c.w = fmaxf(c.w, 0.f);
        d.x = fmaxf(d.x, 0.f); d.y = fmaxf(d.y, 0.f); d.z = fmaxf(d.z, 0.f); d.w = fmaxf(d.w, 0.f);
        __stcs(&out[i],              a);
        __stcs(&out[i + stride],     b);
        __stcs(&out[i + 2 * stride], c);
        __stcs(&out[i + 3 * stride], d);
    }
    for (; i < n4; i += stride) {
        float4 a = __ldg(&in[i]);
        a.x = fmaxf(a.x, 0.f); a.y = fmaxf(a.y, 0.f);
        a.z = fmaxf(a.z, 0.f); a.w = fmaxf(a.w, 0.f);
        __stcs(&out[i], a);
    }
}

__global__ __launch_bounds__(256) void relu_scalar_kernel(
    const float* __restrict__ in, float* __restrict__ out, int n, int start)
{
    int i = start + blockIdx.x * blockDim.x + threadIdx.x;
    if (i < n) out[i] = fmaxf(__ldg(&in[i]), 0.f);
}

extern "C" void kernel_launch(void* const* d_in, const int* in_sizes, int n_in,
                              void* d_out, int out_size)
{
    const float* in = (const float*)d_in[0];
    float* out = (float*)d_out;
    int n = in_sizes[0];

    int n4 = n / 4;
    if (n4 > 0) {
        const int threads = 256;
        int blocks = 148 * 8;   // one full wave at occ 8
        int needed = (n4 + threads - 1) / threads;
        if (blocks > needed) blocks = needed;
        relu_f4_kernel<<<blocks, threads>>>(
            (const float4*)in, (float4*)out, n4);
    }
    int rem = n - n4 * 4;
    if (rem > 0) {
        relu_scalar_kernel<<<(rem + 255) / 256, 256>>>(in, out, n, n4 * 4);
    }
}